// round 1
// baseline (speedup 1.0000x reference)
#include <cuda_runtime.h>

// Problem constants (fixed shapes per reference):
//   x:  [1024, 1024] f32
//   eps:[100, 1024, 1024] f32
//   m:  [1024, 1024] f32
//   s:  [1024, 1024] f32
//   out:[1024, 1024] f32
// out = x @ W  where  W = m + softplus(s) * mean_k(eps)

#define B_DIM 1024
#define IN_DIM 1024
#define OUT_DIM 1024
#define K_SAMPLES 100

// Scratch for the effective weight matrix (allocation-free rule: device global).
__device__ float d_W[IN_DIM * OUT_DIM];

// ---------------------------------------------------------------------------
// Kernel 1: W[j,l] = m[j,l] + softplus(s[j,l]) * (1/K) * sum_k eps[k,j,l]
// Vectorized float4; 262144 float4 elements, one per thread.
// HBM-bound: ~419 MB of eps traffic.
// ---------------------------------------------------------------------------
__global__ void build_w_kernel(const float4* __restrict__ eps,
                               const float4* __restrict__ wm,
                               const float4* __restrict__ ws) {
    const int idx = blockIdx.x * blockDim.x + threadIdx.x;  // 0 .. 262143
    const int PLANE = (IN_DIM * OUT_DIM) / 4;               // float4 per k-plane

    float4 a0 = make_float4(0.f, 0.f, 0.f, 0.f);
    float4 a1 = make_float4(0.f, 0.f, 0.f, 0.f);
    float4 a2 = make_float4(0.f, 0.f, 0.f, 0.f);
    float4 a3 = make_float4(0.f, 0.f, 0.f, 0.f);

    const float4* p = eps + idx;
#pragma unroll 1
    for (int k = 0; k < K_SAMPLES; k += 4) {
        float4 e0 = p[(k + 0) * PLANE];
        float4 e1 = p[(k + 1) * PLANE];
        float4 e2 = p[(k + 2) * PLANE];
        float4 e3 = p[(k + 3) * PLANE];
        a0.x += e0.x; a0.y += e0.y; a0.z += e0.z; a0.w += e0.w;
        a1.x += e1.x; a1.y += e1.y; a1.z += e1.z; a1.w += e1.w;
        a2.x += e2.x; a2.y += e2.y; a2.z += e2.z; a2.w += e2.w;
        a3.x += e3.x; a3.y += e3.y; a3.z += e3.z; a3.w += e3.w;
    }
    float4 acc;
    acc.x = (a0.x + a1.x) + (a2.x + a3.x);
    acc.y = (a0.y + a1.y) + (a2.y + a3.y);
    acc.z = (a0.z + a1.z) + (a2.z + a3.z);
    acc.w = (a0.w + a1.w) + (a2.w + a3.w);

    const float inv_k = 1.0f / (float)K_SAMPLES;
    float4 m4 = wm[idx];
    float4 s4 = ws[idx];

    // softplus(x) = max(x,0) + log1p(exp(-|x|))  (stable; matches jax.nn.softplus)
    float sp_x = fmaxf(s4.x, 0.f) + log1pf(expf(-fabsf(s4.x)));
    float sp_y = fmaxf(s4.y, 0.f) + log1pf(expf(-fabsf(s4.y)));
    float sp_z = fmaxf(s4.z, 0.f) + log1pf(expf(-fabsf(s4.z)));
    float sp_w = fmaxf(s4.w, 0.f) + log1pf(expf(-fabsf(s4.w)));

    float4 w4;
    w4.x = fmaf(sp_x, acc.x * inv_k, m4.x);
    w4.y = fmaf(sp_y, acc.y * inv_k, m4.y);
    w4.z = fmaf(sp_z, acc.z * inv_k, m4.z);
    w4.w = fmaf(sp_w, acc.w * inv_k, m4.w);

    reinterpret_cast<float4*>(d_W)[idx] = w4;
}

// ---------------------------------------------------------------------------
// Kernel 2: out = x @ W    (1024x1024x1024 fp32, tiled SIMT GEMM)
// 128x128 block tile, BK=8, 256 threads, 8x8 micro-tile per thread
// with the 64-spread layout (rows {tm..tm+3, tm+64..}, cols likewise)
// for conflict-free LDS.128.
// ---------------------------------------------------------------------------
#define BM 128
#define BN 128
#define BK 8

__global__ __launch_bounds__(256, 2)
void gemm_kernel(const float* __restrict__ A,   // x, [1024,1024] row-major
                 float* __restrict__ C) {       // out, [1024,1024]
    __shared__ float As[BK][BM];   // transposed A tile: As[k][m]
    __shared__ float Bs[BK][BN];   // Bs[k][n]

    const int tid = threadIdx.x;
    const int bm = blockIdx.y * BM;
    const int bn = blockIdx.x * BN;

    // A tile load mapping: 128 rows x 8 k -> 256 float4
    const int arow = tid >> 1;           // 0..127
    const int aseg = (tid & 1) * 4;      // k offset 0 or 4
    // B tile load mapping: 8 k-rows x 128 n -> 256 float4
    const int brow = tid >> 5;           // 0..7
    const int bcol = (tid & 31) * 4;     // 0..124

    // compute mapping
    const int tm = (tid >> 4) * 4;       // 0..60
    const int tn = (tid & 15) * 4;       // 0..60

    float acc[8][8];
#pragma unroll
    for (int i = 0; i < 8; i++)
#pragma unroll
        for (int j = 0; j < 8; j++) acc[i][j] = 0.f;

    const float* Bmat = d_W;

    for (int k0 = 0; k0 < IN_DIM; k0 += BK) {
        float4 av = *reinterpret_cast<const float4*>(
            &A[(bm + arow) * IN_DIM + k0 + aseg]);
        float4 bv = *reinterpret_cast<const float4*>(
            &Bmat[(k0 + brow) * OUT_DIM + bn + bcol]);

        As[aseg + 0][arow] = av.x;
        As[aseg + 1][arow] = av.y;
        As[aseg + 2][arow] = av.z;
        As[aseg + 3][arow] = av.w;
        *reinterpret_cast<float4*>(&Bs[brow][bcol]) = bv;

        __syncthreads();

#pragma unroll
        for (int kk = 0; kk < BK; kk++) {
            float4 a0 = *reinterpret_cast<const float4*>(&As[kk][tm]);
            float4 a1 = *reinterpret_cast<const float4*>(&As[kk][tm + 64]);
            float4 b0 = *reinterpret_cast<const float4*>(&Bs[kk][tn]);
            float4 b1 = *reinterpret_cast<const float4*>(&Bs[kk][tn + 64]);

            const float ar[8] = {a0.x, a0.y, a0.z, a0.w, a1.x, a1.y, a1.z, a1.w};
            const float br[8] = {b0.x, b0.y, b0.z, b0.w, b1.x, b1.y, b1.z, b1.w};
#pragma unroll
            for (int i = 0; i < 8; i++)
#pragma unroll
                for (int j = 0; j < 8; j++)
                    acc[i][j] = fmaf(ar[i], br[j], acc[i][j]);
        }
        __syncthreads();
    }

    // Write out: rows {bm+tm+0..3, bm+64+tm+0..3}, cols {bn+tn.., bn+64+tn..}
#pragma unroll
    for (int i = 0; i < 8; i++) {
        int row = bm + tm + (i < 4 ? i : 64 + (i - 4));
        float4 v0 = make_float4(acc[i][0], acc[i][1], acc[i][2], acc[i][3]);
        float4 v1 = make_float4(acc[i][4], acc[i][5], acc[i][6], acc[i][7]);
        *reinterpret_cast<float4*>(&C[row * OUT_DIM + bn + tn]) = v0;
        *reinterpret_cast<float4*>(&C[row * OUT_DIM + bn + 64 + tn]) = v1;
    }
}

extern "C" void kernel_launch(void* const* d_in, const int* in_sizes, int n_in,
                              void* d_out, int out_size) {
    const float* x   = (const float*)d_in[0];   // [1024,1024]
    const float* eps = (const float*)d_in[1];   // [100,1024,1024]
    const float* wm  = (const float*)d_in[2];   // [1024,1024]
    const float* ws  = (const float*)d_in[3];   // [1024,1024]
    float* out = (float*)d_out;                 // [1024,1024]

    // Kernel 1: build effective weights W into d_W
    const int n4 = (IN_DIM * OUT_DIM) / 4;      // 262144 float4
    build_w_kernel<<<n4 / 256, 256>>>(
        (const float4*)eps, (const float4*)wm, (const float4*)ws);

    // Kernel 2: out = x @ W
    dim3 grid(OUT_DIM / BN, B_DIM / BM);        // (8, 8)
    gemm_kernel<<<grid, 256>>>(x, out);
}

// round 3
// speedup vs baseline: 1.9447x; 1.9447x over previous
#include <cuda_runtime.h>
#include <cuda_bf16.h>
#include <cstdint>

// out = x @ W,  W = m + softplus(s) * mean_k(eps)
// x:[1024,1024] eps:[100,1024,1024] m,s:[1024,1024] out:[1024,1024], all f32.
//
// K1 build_w     : W (f32)               — HBM roofline (~63us, 419MB eps)
// K2 convert_x   : x -> x_hi + x_lo bf16
// K3 transpose_w : W -> W^T bf16 hi/lo   ([N,K], K-contiguous)
// K4 gemm_mma    : mma.sync bf16 3-split (Ah*Bh + Ah*Bl + Al*Bh), f32 accum
//    (tcgen05 rejected by this toolchain's PTX target; HMMA path instead)

#define B_DIM 1024
#define IN_DIM 1024
#define OUT_DIM 1024
#define K_SAMPLES 100

__device__ float          d_W[IN_DIM * OUT_DIM];
__device__ __nv_bfloat16  d_xhi[B_DIM * IN_DIM];
__device__ __nv_bfloat16  d_xlo[B_DIM * IN_DIM];
__device__ __nv_bfloat16  d_wthi[OUT_DIM * IN_DIM];   // W^T: [l][j]
__device__ __nv_bfloat16  d_wtlo[OUT_DIM * IN_DIM];

// ---------------------------------------------------------------------------
// K1: W[j,l] = m + softplus(s) * mean_k eps   (HBM roofline, unchanged)
// ---------------------------------------------------------------------------
__global__ void build_w_kernel(const float4* __restrict__ eps,
                               const float4* __restrict__ wm,
                               const float4* __restrict__ ws) {
    const int idx = blockIdx.x * blockDim.x + threadIdx.x;
    const int PLANE = (IN_DIM * OUT_DIM) / 4;

    float4 a0 = make_float4(0.f, 0.f, 0.f, 0.f);
    float4 a1 = a0, a2 = a0, a3 = a0;

    const float4* p = eps + idx;
#pragma unroll 1
    for (int k = 0; k < K_SAMPLES; k += 4) {
        float4 e0 = p[(k + 0) * PLANE];
        float4 e1 = p[(k + 1) * PLANE];
        float4 e2 = p[(k + 2) * PLANE];
        float4 e3 = p[(k + 3) * PLANE];
        a0.x += e0.x; a0.y += e0.y; a0.z += e0.z; a0.w += e0.w;
        a1.x += e1.x; a1.y += e1.y; a1.z += e1.z; a1.w += e1.w;
        a2.x += e2.x; a2.y += e2.y; a2.z += e2.z; a2.w += e2.w;
        a3.x += e3.x; a3.y += e3.y; a3.z += e3.z; a3.w += e3.w;
    }
    float4 acc;
    acc.x = (a0.x + a1.x) + (a2.x + a3.x);
    acc.y = (a0.y + a1.y) + (a2.y + a3.y);
    acc.z = (a0.z + a1.z) + (a2.z + a3.z);
    acc.w = (a0.w + a1.w) + (a2.w + a3.w);

    const float inv_k = 1.0f / (float)K_SAMPLES;
    float4 m4 = wm[idx];
    float4 s4 = ws[idx];

    float sp_x = fmaxf(s4.x, 0.f) + log1pf(expf(-fabsf(s4.x)));
    float sp_y = fmaxf(s4.y, 0.f) + log1pf(expf(-fabsf(s4.y)));
    float sp_z = fmaxf(s4.z, 0.f) + log1pf(expf(-fabsf(s4.z)));
    float sp_w = fmaxf(s4.w, 0.f) + log1pf(expf(-fabsf(s4.w)));

    float4 w4;
    w4.x = fmaf(sp_x, acc.x * inv_k, m4.x);
    w4.y = fmaf(sp_y, acc.y * inv_k, m4.y);
    w4.z = fmaf(sp_z, acc.z * inv_k, m4.z);
    w4.w = fmaf(sp_w, acc.w * inv_k, m4.w);

    reinterpret_cast<float4*>(d_W)[idx] = w4;
}

// ---------------------------------------------------------------------------
// K2: x -> (x_hi, x_lo) bf16
// ---------------------------------------------------------------------------
__global__ void convert_x_kernel(const float4* __restrict__ x) {
    const int idx = blockIdx.x * blockDim.x + threadIdx.x;
    float4 v = x[idx];
    __nv_bfloat16 h0 = __float2bfloat16_rn(v.x);
    __nv_bfloat16 h1 = __float2bfloat16_rn(v.y);
    __nv_bfloat16 h2 = __float2bfloat16_rn(v.z);
    __nv_bfloat16 h3 = __float2bfloat16_rn(v.w);
    __nv_bfloat16 l0 = __float2bfloat16_rn(v.x - __bfloat162float(h0));
    __nv_bfloat16 l1 = __float2bfloat16_rn(v.y - __bfloat162float(h1));
    __nv_bfloat16 l2 = __float2bfloat16_rn(v.z - __bfloat162float(h2));
    __nv_bfloat16 l3 = __float2bfloat16_rn(v.w - __bfloat162float(h3));
    __nv_bfloat162* hp = reinterpret_cast<__nv_bfloat162*>(d_xhi) + idx * 2;
    __nv_bfloat162* lp = reinterpret_cast<__nv_bfloat162*>(d_xlo) + idx * 2;
    hp[0] = __nv_bfloat162(h0, h1);
    hp[1] = __nv_bfloat162(h2, h3);
    lp[0] = __nv_bfloat162(l0, l1);
    lp[1] = __nv_bfloat162(l2, l3);
}

// ---------------------------------------------------------------------------
// K3: W [j,l] -> W^T [l,j] split bf16 hi/lo (32x32 smem tiles)
// ---------------------------------------------------------------------------
__global__ void transpose_w_kernel() {
    __shared__ float t[32][33];
    const int l0 = blockIdx.x * 32;
    const int j0 = blockIdx.y * 32;
    const int tx = threadIdx.x, ty = threadIdx.y;
#pragma unroll
    for (int i = 0; i < 4; i++)
        t[ty + i * 8][tx] = d_W[(j0 + ty + i * 8) * OUT_DIM + l0 + tx];
    __syncthreads();
#pragma unroll
    for (int i = 0; i < 4; i++) {
        float v = t[tx][ty + i * 8];
        __nv_bfloat16 hi = __float2bfloat16_rn(v);
        __nv_bfloat16 lo = __float2bfloat16_rn(v - __bfloat162float(hi));
        int o = (l0 + ty + i * 8) * IN_DIM + j0 + tx;
        d_wthi[o] = hi;
        d_wtlo[o] = lo;
    }
}

// ---------------------------------------------------------------------------
// K4: mma.sync bf16 GEMM. CTA 64x128, BK=32, 8 warps (2x4), warp tile 32x32.
// cp.async double buffer; padded smem rows (40 elems) for conflict-free LDSM.
// ---------------------------------------------------------------------------
#define BM 64
#define BN 128
#define BKT 32
#define RS 40                       // smem row stride (elems) -> 80B
#define OFF_AH 0
#define OFF_AL (BM * RS * 2)        // 5120
#define OFF_BH (2 * BM * RS * 2)    // 10240
#define OFF_BL (OFF_BH + BN * RS * 2)  // 20480
#define STAGE_BYTES (OFF_BH + 2 * BN * RS * 2)  // 30720
#define GEMM_SMEM (2 * STAGE_BYTES)             // 61440
#define NKT (IN_DIM / BKT)          // 32

__device__ __forceinline__ uint32_t smem_u32(const void* p) {
    uint32_t a;
    asm("{ .reg .u64 t; cvta.to.shared.u64 t, %1; cvt.u32.u64 %0, t; }"
        : "=r"(a) : "l"(p));
    return a;
}

__device__ __forceinline__ void cp16(uint32_t dst, const void* src) {
    asm volatile("cp.async.cg.shared.global [%0], [%1], 16;"
                 :: "r"(dst), "l"(__cvta_generic_to_global(src)) : "memory");
}

__device__ __forceinline__ void ldm4(uint32_t addr, uint32_t r[4]) {
    asm volatile("ldmatrix.sync.aligned.m8n8.x4.shared.b16 {%0,%1,%2,%3}, [%4];"
                 : "=r"(r[0]), "=r"(r[1]), "=r"(r[2]), "=r"(r[3]) : "r"(addr));
}

__device__ __forceinline__ void mma_bf16(float c[4], const uint32_t a[4],
                                         const uint32_t b[2]) {
    asm volatile(
        "mma.sync.aligned.m16n8k16.row.col.f32.bf16.bf16.f32 "
        "{%0,%1,%2,%3}, {%4,%5,%6,%7}, {%8,%9}, {%0,%1,%2,%3};"
        : "+f"(c[0]), "+f"(c[1]), "+f"(c[2]), "+f"(c[3])
        : "r"(a[0]), "r"(a[1]), "r"(a[2]), "r"(a[3]), "r"(b[0]), "r"(b[1]));
}

__device__ __forceinline__ void load_stage(uint32_t st, int bm, int bn,
                                           int k0, int tid) {
    const int row = tid >> 2;       // 0..63
    const int ch = tid & 3;         // 16B chunk in 32-elem row
    const int gk = k0 + ch * 8;
    cp16(st + OFF_AH + row * (RS * 2) + ch * 16,
         d_xhi + (bm + row) * IN_DIM + gk);
    cp16(st + OFF_AL + row * (RS * 2) + ch * 16,
         d_xlo + (bm + row) * IN_DIM + gk);
    cp16(st + OFF_BH + row * (RS * 2) + ch * 16,
         d_wthi + (bn + row) * IN_DIM + gk);
    cp16(st + OFF_BH + (row + 64) * (RS * 2) + ch * 16,
         d_wthi + (bn + row + 64) * IN_DIM + gk);
    cp16(st + OFF_BL + row * (RS * 2) + ch * 16,
         d_wtlo + (bn + row) * IN_DIM + gk);
    cp16(st + OFF_BL + (row + 64) * (RS * 2) + ch * 16,
         d_wtlo + (bn + row + 64) * IN_DIM + gk);
}

__global__ __launch_bounds__(256, 1)
void gemm_mma_kernel(float* __restrict__ out) {
    extern __shared__ char smem[];
    const uint32_t sbase = smem_u32(smem);
    const int tid = threadIdx.x;
    const int lane = tid & 31;
    const int wid = tid >> 5;
    const int wm = wid & 1;         // 0..1  (32-row half)
    const int wn = wid >> 1;        // 0..3  (32-col quarter)

    const int bm = blockIdx.y * BM;
    const int bn = blockIdx.x * BN;

    float acc[2][4][4];
#pragma unroll
    for (int i = 0; i < 2; i++)
#pragma unroll
        for (int j = 0; j < 4; j++)
#pragma unroll
            for (int k = 0; k < 4; k++) acc[i][j][k] = 0.f;

    // A-frag ldmatrix addressing: lanes 0-15 -> rows, lanes 16-31 -> rows, k+8
    const int ar = lane & 15;
    const int ak = (lane >> 4) * 8;
    // B-frag ldmatrix addressing: 4 groups of 8 lanes
    const int bg = lane >> 3;
    const int bi = lane & 7;
    const int bn_off = ((bg >> 1) & 1) * 8;   // groups 2,3 -> n+8
    const int bk_off = (bg & 1) * 8;          // groups 1,3 -> k+8

    load_stage(sbase, bm, bn, 0, tid);
    asm volatile("cp.async.commit_group;" ::: "memory");

#pragma unroll 1
    for (int t = 0; t < NKT; ++t) {
        if (t + 1 < NKT) {
            load_stage(sbase + ((t + 1) & 1) * STAGE_BYTES, bm, bn,
                       (t + 1) * BKT, tid);
            asm volatile("cp.async.commit_group;" ::: "memory");
            asm volatile("cp.async.wait_group 1;" ::: "memory");
        } else {
            asm volatile("cp.async.wait_group 0;" ::: "memory");
        }
        __syncthreads();

        const uint32_t st = sbase + (t & 1) * STAGE_BYTES;

#pragma unroll
        for (int ks = 0; ks < 2; ks++) {
            uint32_t ah[2][4], al[2][4], bh[4][2], bl[4][2];
#pragma unroll
            for (int mh = 0; mh < 2; mh++) {
                const int row = wm * 32 + mh * 16 + ar;
                const uint32_t ad =
                    st + OFF_AH + row * (RS * 2) + (ks * 16 + ak) * 2;
                ldm4(ad, ah[mh]);
                ldm4(ad + (OFF_AL - OFF_AH), al[mh]);
            }
#pragma unroll
            for (int q = 0; q < 2; q++) {
                const int n = wn * 32 + q * 16 + bn_off + bi;
                const int kk = ks * 16 + bk_off;
                const uint32_t bd = st + OFF_BH + n * (RS * 2) + kk * 2;
                uint32_t tmp[4];
                ldm4(bd, tmp);
                bh[2 * q][0] = tmp[0]; bh[2 * q][1] = tmp[1];
                bh[2 * q + 1][0] = tmp[2]; bh[2 * q + 1][1] = tmp[3];
                ldm4(bd + (OFF_BL - OFF_BH), tmp);
                bl[2 * q][0] = tmp[0]; bl[2 * q][1] = tmp[1];
                bl[2 * q + 1][0] = tmp[2]; bl[2 * q + 1][1] = tmp[3];
            }
#pragma unroll
            for (int mh = 0; mh < 2; mh++)
#pragma unroll
                for (int nf = 0; nf < 4; nf++) {
                    mma_bf16(acc[mh][nf], ah[mh], bh[nf]);
                    mma_bf16(acc[mh][nf], ah[mh], bl[nf]);
                    mma_bf16(acc[mh][nf], al[mh], bh[nf]);
                }
        }
        __syncthreads();
    }

    // Epilogue: direct STG (c-frag layout: rows l/4 & +8, cols 2*(l%4))
    const int crow = lane >> 2;
    const int ccol = (lane & 3) * 2;
#pragma unroll
    for (int mh = 0; mh < 2; mh++) {
#pragma unroll
        for (int nf = 0; nf < 4; nf++) {
            const int row = bm + wm * 32 + mh * 16 + crow;
            const int col = bn + wn * 32 + nf * 8 + ccol;
            *reinterpret_cast<float2*>(&out[row * OUT_DIM + col]) =
                make_float2(acc[mh][nf][0], acc[mh][nf][1]);
            *reinterpret_cast<float2*>(&out[(row + 8) * OUT_DIM + col]) =
                make_float2(acc[mh][nf][2], acc[mh][nf][3]);
        }
    }
}

// ---------------------------------------------------------------------------
extern "C" void kernel_launch(void* const* d_in, const int* in_sizes, int n_in,
                              void* d_out, int out_size) {
    const float* x   = (const float*)d_in[0];
    const float* eps = (const float*)d_in[1];
    const float* wm  = (const float*)d_in[2];
    const float* ws  = (const float*)d_in[3];
    float* out = (float*)d_out;

    cudaFuncSetAttribute(gemm_mma_kernel,
                         cudaFuncAttributeMaxDynamicSharedMemorySize,
                         GEMM_SMEM);

    const int n4 = (IN_DIM * OUT_DIM) / 4;
    convert_x_kernel<<<n4 / 256, 256>>>((const float4*)x);
    build_w_kernel<<<n4 / 256, 256>>>((const float4*)eps,
                                      (const float4*)wm, (const float4*)ws);
    transpose_w_kernel<<<dim3(32, 32), dim3(32, 8)>>>();

    dim3 grid(OUT_DIM / BN, B_DIM / BM);  // (8, 16) = 128 CTAs
    gemm_mma_kernel<<<grid, 256, GEMM_SMEM>>>(out);
}

// round 5
// speedup vs baseline: 2.0786x; 1.0688x over previous
#include <cuda_runtime.h>
#include <cuda_bf16.h>
#include <cstdint>

// out = x @ W,  W = m + softplus(s) * mean_k(eps)
// x:[1024,1024] eps:[100,1024,1024] m,s:[1024,1024] out:[1024,1024] f32.
//
// K1 prep: blocks [0,1024)   -> W split to bf16 hi/lo in [k][n] layout
//          blocks [1024,2048)-> x  split to bf16 hi/lo in [m][k] layout
// K2 gemm: mma.sync bf16 3-split (Ah*Bh + Ah*Bl + Al*Bh), f32 accum,
//          4-stage cp.async pipeline, B frags via ldmatrix.trans.

#define B_DIM 1024
#define IN_DIM 1024
#define OUT_DIM 1024
#define K_SAMPLES 100

__device__ __nv_bfloat16  d_xhi[B_DIM * IN_DIM];
__device__ __nv_bfloat16  d_xlo[B_DIM * IN_DIM];
__device__ __nv_bfloat16  d_whi[IN_DIM * OUT_DIM];   // [k][n] (same as W[j,l])
__device__ __nv_bfloat16  d_wlo[IN_DIM * OUT_DIM];

// ---------------------------------------------------------------------------
// K1: fused prep
// ---------------------------------------------------------------------------
__global__ void prep_kernel(const float4* __restrict__ x,
                            const float4* __restrict__ eps,
                            const float4* __restrict__ wm,
                            const float4* __restrict__ ws) {
    const int bid = blockIdx.x;
    if (bid < 1024) {
        // ---- build W -> hi/lo bf16, [k][n] layout (coalesced) ----
        const int idx = bid * blockDim.x + threadIdx.x;   // float4 index
        const int PLANE = (IN_DIM * OUT_DIM) / 4;

        float4 a0 = make_float4(0.f, 0.f, 0.f, 0.f);
        float4 a1 = a0, a2 = a0, a3 = a0;
        const float4* p = eps + idx;
#pragma unroll 1
        for (int k = 0; k < K_SAMPLES; k += 4) {
            float4 e0 = p[(k + 0) * PLANE];
            float4 e1 = p[(k + 1) * PLANE];
            float4 e2 = p[(k + 2) * PLANE];
            float4 e3 = p[(k + 3) * PLANE];
            a0.x += e0.x; a0.y += e0.y; a0.z += e0.z; a0.w += e0.w;
            a1.x += e1.x; a1.y += e1.y; a1.z += e1.z; a1.w += e1.w;
            a2.x += e2.x; a2.y += e2.y; a2.z += e2.z; a2.w += e2.w;
            a3.x += e3.x; a3.y += e3.y; a3.z += e3.z; a3.w += e3.w;
        }
        float4 acc;
        acc.x = (a0.x + a1.x) + (a2.x + a3.x);
        acc.y = (a0.y + a1.y) + (a2.y + a3.y);
        acc.z = (a0.z + a1.z) + (a2.z + a3.z);
        acc.w = (a0.w + a1.w) + (a2.w + a3.w);

        const float inv_k = 1.0f / (float)K_SAMPLES;
        float4 m4 = wm[idx];
        float4 s4 = ws[idx];

        float sp_x = fmaxf(s4.x, 0.f) + log1pf(expf(-fabsf(s4.x)));
        float sp_y = fmaxf(s4.y, 0.f) + log1pf(expf(-fabsf(s4.y)));
        float sp_z = fmaxf(s4.z, 0.f) + log1pf(expf(-fabsf(s4.z)));
        float sp_w = fmaxf(s4.w, 0.f) + log1pf(expf(-fabsf(s4.w)));

        float wx = fmaf(sp_x, acc.x * inv_k, m4.x);
        float wy = fmaf(sp_y, acc.y * inv_k, m4.y);
        float wz = fmaf(sp_z, acc.z * inv_k, m4.z);
        float ww = fmaf(sp_w, acc.w * inv_k, m4.w);

        __nv_bfloat16 hx = __float2bfloat16_rn(wx);
        __nv_bfloat16 hy = __float2bfloat16_rn(wy);
        __nv_bfloat16 hz = __float2bfloat16_rn(wz);
        __nv_bfloat16 hw = __float2bfloat16_rn(ww);
        __nv_bfloat16 lx = __float2bfloat16_rn(wx - __bfloat162float(hx));
        __nv_bfloat16 ly = __float2bfloat16_rn(wy - __bfloat162float(hy));
        __nv_bfloat16 lz = __float2bfloat16_rn(wz - __bfloat162float(hz));
        __nv_bfloat16 lw = __float2bfloat16_rn(ww - __bfloat162float(hw));

        __nv_bfloat162* hp = reinterpret_cast<__nv_bfloat162*>(d_whi) + idx * 2;
        __nv_bfloat162* lp = reinterpret_cast<__nv_bfloat162*>(d_wlo) + idx * 2;
        hp[0] = __nv_bfloat162(hx, hy);
        hp[1] = __nv_bfloat162(hz, hw);
        lp[0] = __nv_bfloat162(lx, ly);
        lp[1] = __nv_bfloat162(lz, lw);
    } else {
        // ---- x -> hi/lo bf16 ----
        const int idx = (bid - 1024) * blockDim.x + threadIdx.x;
        float4 v = x[idx];
        __nv_bfloat16 h0 = __float2bfloat16_rn(v.x);
        __nv_bfloat16 h1 = __float2bfloat16_rn(v.y);
        __nv_bfloat16 h2 = __float2bfloat16_rn(v.z);
        __nv_bfloat16 h3 = __float2bfloat16_rn(v.w);
        __nv_bfloat16 l0 = __float2bfloat16_rn(v.x - __bfloat162float(h0));
        __nv_bfloat16 l1 = __float2bfloat16_rn(v.y - __bfloat162float(h1));
        __nv_bfloat16 l2 = __float2bfloat16_rn(v.z - __bfloat162float(h2));
        __nv_bfloat16 l3 = __float2bfloat16_rn(v.w - __bfloat162float(h3));
        __nv_bfloat162* hp = reinterpret_cast<__nv_bfloat162*>(d_xhi) + idx * 2;
        __nv_bfloat162* lp = reinterpret_cast<__nv_bfloat162*>(d_xlo) + idx * 2;
        hp[0] = __nv_bfloat162(h0, h1);
        hp[1] = __nv_bfloat162(h2, h3);
        lp[0] = __nv_bfloat162(l0, l1);
        lp[1] = __nv_bfloat162(l2, l3);
    }
}

// ---------------------------------------------------------------------------
// K2: mma.sync bf16 GEMM. CTA 64x128, BK=32, 8 warps (2x4), warp tile 32x32.
// 4-stage cp.async pipeline, one __syncthreads per k-tile.
// A smem [m][k] pad40; B smem [k][n] pad136 (ldmatrix.trans).
// ---------------------------------------------------------------------------
#define BM 64
#define BN 128
#define BKT 32
#define NKT (IN_DIM / BKT)          // 32
#define NSTAGE 4
#define RSA 80                      // A row stride bytes (40 elems)
#define RSB 272                     // B row stride bytes (136 elems)
#define OFF_AH 0
#define OFF_AL (BM * RSA)                       // 5120
#define OFF_BH (2 * BM * RSA)                   // 10240
#define OFF_BL (OFF_BH + BKT * RSB)             // 18944
#define STAGE_BYTES (OFF_BH + 2 * BKT * RSB)    // 27648
#define GEMM_SMEM (NSTAGE * STAGE_BYTES)        // 110592

__device__ __forceinline__ uint32_t smem_u32(const void* p) {
    uint32_t a;
    asm("{ .reg .u64 t; cvta.to.shared.u64 t, %1; cvt.u32.u64 %0, t; }"
        : "=r"(a) : "l"(p));
    return a;
}
__device__ __forceinline__ void cp16(uint32_t dst, const void* src) {
    asm volatile("cp.async.cg.shared.global [%0], [%1], 16;"
                 :: "r"(dst), "l"(__cvta_generic_to_global(src)) : "memory");
}
__device__ __forceinline__ void ldm4(uint32_t addr, uint32_t r[4]) {
    asm volatile("ldmatrix.sync.aligned.m8n8.x4.shared.b16 {%0,%1,%2,%3}, [%4];"
                 : "=r"(r[0]), "=r"(r[1]), "=r"(r[2]), "=r"(r[3]) : "r"(addr));
}
__device__ __forceinline__ void ldm4t(uint32_t addr, uint32_t r[4]) {
    asm volatile("ldmatrix.sync.aligned.m8n8.x4.trans.shared.b16 {%0,%1,%2,%3}, [%4];"
                 : "=r"(r[0]), "=r"(r[1]), "=r"(r[2]), "=r"(r[3]) : "r"(addr));
}
__device__ __forceinline__ void mma_bf16(float c[4], const uint32_t a[4],
                                         const uint32_t b[2]) {
    asm volatile(
        "mma.sync.aligned.m16n8k16.row.col.f32.bf16.bf16.f32 "
        "{%0,%1,%2,%3}, {%4,%5,%6,%7}, {%8,%9}, {%0,%1,%2,%3};"
        : "+f"(c[0]), "+f"(c[1]), "+f"(c[2]), "+f"(c[3])
        : "r"(a[0]), "r"(a[1]), "r"(a[2]), "r"(a[3]), "r"(b[0]), "r"(b[1]));
}

__device__ __forceinline__ void load_stage(uint32_t st, int bm, int bn,
                                           int k0, int tid) {
    // A: 64 rows x 32 k (hi+lo).  One 16B chunk x2 per thread.
    {
        const int row = tid >> 2;          // 0..63
        const int ch = tid & 3;            // 0..3
        const int gk = k0 + ch * 8;
        cp16(st + OFF_AH + row * RSA + ch * 16,
             d_xhi + (bm + row) * IN_DIM + gk);
        cp16(st + OFF_AL + row * RSA + ch * 16,
             d_xlo + (bm + row) * IN_DIM + gk);
    }
    // B: 32 k-rows x 128 n (hi+lo), [k][n] layout. Two 16B chunks x2 per thread.
    {
        const int row = tid >> 3;          // 0..31
        const int ch = tid & 7;            // 0..7  (chunks ch and ch+8)
        const __nv_bfloat16* sh = d_whi + (k0 + row) * OUT_DIM + bn;
        const __nv_bfloat16* sl = d_wlo + (k0 + row) * OUT_DIM + bn;
        cp16(st + OFF_BH + row * RSB + ch * 16,        sh + ch * 8);
        cp16(st + OFF_BH + row * RSB + (ch + 8) * 16,  sh + (ch + 8) * 8);
        cp16(st + OFF_BL + row * RSB + ch * 16,        sl + ch * 8);
        cp16(st + OFF_BL + row * RSB + (ch + 8) * 16,  sl + (ch + 8) * 8);
    }
}

__global__ __launch_bounds__(256, 1)
void gemm_mma_kernel(float* __restrict__ out) {
    extern __shared__ char smem[];
    const uint32_t sbase = smem_u32(smem);
    const int tid = threadIdx.x;
    const int lane = tid & 31;
    const int wid = tid >> 5;
    const int wm = wid & 1;         // 32-row half
    const int wn = wid >> 1;        // 32-col quarter

    const int bm = blockIdx.y * BM;
    const int bn = blockIdx.x * BN;

    float acc[2][4][4];
#pragma unroll
    for (int i = 0; i < 2; i++)
#pragma unroll
        for (int j = 0; j < 4; j++)
#pragma unroll
            for (int k = 0; k < 4; k++) acc[i][j][k] = 0.f;

    // A ldmatrix addressing (non-trans, [m][k]):
    const int ar = lane & 15;              // row within 16
    const int ak = (lane >> 4) * 8;        // k offset 0/8
    // B ldmatrix addressing (trans, [k][n]):
    const int bkr = (lane & 7) + ((lane >> 3) & 1) * 8;  // k row 0..15
    const int bnc = (lane >> 4) * 8;                     // n offset 0/8

#pragma unroll
    for (int s = 0; s < NSTAGE - 1; s++) {
        load_stage(sbase + s * STAGE_BYTES, bm, bn, s * BKT, tid);
        asm volatile("cp.async.commit_group;" ::: "memory");
    }

#pragma unroll 1
    for (int t = 0; t < NKT; ++t) {
        if (t <= NKT - NSTAGE)
            asm volatile("cp.async.wait_group %0;" :: "n"(NSTAGE - 2) : "memory");
        else
            asm volatile("cp.async.wait_group 0;" ::: "memory");
        __syncthreads();

        if (t + NSTAGE - 1 < NKT) {
            load_stage(sbase + ((t + NSTAGE - 1) % NSTAGE) * STAGE_BYTES,
                       bm, bn, (t + NSTAGE - 1) * BKT, tid);
            asm volatile("cp.async.commit_group;" ::: "memory");
        }

        const uint32_t st = sbase + (t % NSTAGE) * STAGE_BYTES;

#pragma unroll
        for (int ks = 0; ks < 2; ks++) {
            uint32_t ah[2][4], al[2][4], bh[4][2], bl[4][2];
#pragma unroll
            for (int mh = 0; mh < 2; mh++) {
                const int row = wm * 32 + mh * 16 + ar;
                const uint32_t ad = st + OFF_AH + row * RSA + (ks * 16 + ak) * 2;
                ldm4(ad, ah[mh]);
                ldm4(ad + (OFF_AL - OFF_AH), al[mh]);
            }
#pragma unroll
            for (int q = 0; q < 2; q++) {
                const int krow = ks * 16 + bkr;
                const int ncol = wn * 32 + q * 16 + bnc;
                const uint32_t bd = st + OFF_BH + krow * RSB + ncol * 2;
                uint32_t tmp[4];
                ldm4t(bd, tmp);
                bh[2 * q][0] = tmp[0]; bh[2 * q][1] = tmp[1];
                bh[2 * q + 1][0] = tmp[2]; bh[2 * q + 1][1] = tmp[3];
                ldm4t(bd + (OFF_BL - OFF_BH), tmp);
                bl[2 * q][0] = tmp[0]; bl[2 * q][1] = tmp[1];
                bl[2 * q + 1][0] = tmp[2]; bl[2 * q + 1][1] = tmp[3];
            }
#pragma unroll
            for (int mh = 0; mh < 2; mh++)
#pragma unroll
                for (int nf = 0; nf < 4; nf++) {
                    mma_bf16(acc[mh][nf], ah[mh], bh[nf]);
                    mma_bf16(acc[mh][nf], ah[mh], bl[nf]);
                    mma_bf16(acc[mh][nf], al[mh], bh[nf]);
                }
        }
    }

    // Epilogue: direct STG (c-frag: rows lane/4 & +8, cols 2*(lane%4))
    const int crow = lane >> 2;
    const int ccol = (lane & 3) * 2;
#pragma unroll
    for (int mh = 0; mh < 2; mh++) {
#pragma unroll
        for (int nf = 0; nf < 4; nf++) {
            const int row = bm + wm * 32 + mh * 16 + crow;
            const int col = bn + wn * 32 + nf * 8 + ccol;
            *reinterpret_cast<float2*>(&out[row * OUT_DIM + col]) =
                make_float2(acc[mh][nf][0], acc[mh][nf][1]);
            *reinterpret_cast<float2*>(&out[(row + 8) * OUT_DIM + col]) =
                make_float2(acc[mh][nf][2], acc[mh][nf][3]);
        }
    }
}

// ---------------------------------------------------------------------------
extern "C" void kernel_launch(void* const* d_in, const int* in_sizes, int n_in,
                              void* d_out, int out_size) {
    const float* x   = (const float*)d_in[0];
    const float* eps = (const float*)d_in[1];
    const float* wm  = (const float*)d_in[2];
    const float* ws  = (const float*)d_in[3];
    float* out = (float*)d_out;

    cudaFuncSetAttribute(gemm_mma_kernel,
                         cudaFuncAttributeMaxDynamicSharedMemorySize,
                         GEMM_SMEM);

    prep_kernel<<<2048, 256>>>((const float4*)x, (const float4*)eps,
                               (const float4*)wm, (const float4*)ws);

    dim3 grid(OUT_DIM / BN, B_DIM / BM);  // (8, 16) = 128 CTAs
    gemm_mma_kernel<<<grid, 256, GEMM_SMEM>>>(out);
}